// round 1
// baseline (speedup 1.0000x reference)
#include <cuda_runtime.h>
#include <math.h>

#define NM      4096
#define NPTS    131072
#define GRES    16

// ---- scratch (no allocations allowed) ----
__device__ int g_cnt[NM];
__device__ int g_off[NM];
__device__ int g_start[NM];
__device__ int g_vox[NPTS];
__device__ int g_sorted[NPTS];

__global__ void k_zero() {
    int i = blockIdx.x * blockDim.x + threadIdx.x;
    if (i < NM) g_cnt[i] = 0;
}

__global__ void k_index(const float* __restrict__ pts) {
    int n = blockIdx.x * blockDim.x + threadIdx.x;
    if (n >= NPTS) return;
    float x = pts[3 * n + 0], y = pts[3 * n + 1], z = pts[3 * n + 2];
    int ix = (int)fminf(fmaxf(x * (float)GRES, 0.f), (float)(GRES - 1));
    int iy = (int)fminf(fmaxf(y * (float)GRES, 0.f), (float)(GRES - 1));
    int iz = (int)fminf(fmaxf(z * (float)GRES, 0.f), (float)(GRES - 1));
    int v = ix * (GRES * GRES) + iy * GRES + iz;
    g_vox[n] = v;
    atomicAdd(&g_cnt[v], 1);
}

// one block, 1024 threads, 4 bins each
__global__ void k_scan() {
    __shared__ int sh[1024];
    int t = threadIdx.x;
    int c0 = g_cnt[4 * t + 0], c1 = g_cnt[4 * t + 1];
    int c2 = g_cnt[4 * t + 2], c3 = g_cnt[4 * t + 3];
    int s = c0 + c1 + c2 + c3;
    sh[t] = s;
    __syncthreads();
    for (int d = 1; d < 1024; d <<= 1) {
        int v = (t >= d) ? sh[t - d] : 0;
        __syncthreads();
        sh[t] += v;
        __syncthreads();
    }
    int excl = sh[t] - s;
    g_start[4 * t + 0] = excl; g_off[4 * t + 0] = excl; excl += c0;
    g_start[4 * t + 1] = excl; g_off[4 * t + 1] = excl; excl += c1;
    g_start[4 * t + 2] = excl; g_off[4 * t + 2] = excl; excl += c2;
    g_start[4 * t + 3] = excl; g_off[4 * t + 3] = excl;
}

__global__ void k_scatter() {
    int n = blockIdx.x * blockDim.x + threadIdx.x;
    if (n >= NPTS) return;
    int v = g_vox[n];
    int pos = atomicAdd(&g_off[v], 1);
    g_sorted[pos] = n;
}

// ---- MLP helpers: 32-wide register accumulators, broadcast smem weights ----
__device__ __forceinline__ void acc32(float* a, const float* wrow, float v) {
    const float4* w4 = reinterpret_cast<const float4*>(wrow);
#pragma unroll
    for (int j = 0; j < 8; j++) {
        float4 w = w4[j];
        a[4 * j + 0] = fmaf(v, w.x, a[4 * j + 0]);
        a[4 * j + 1] = fmaf(v, w.y, a[4 * j + 1]);
        a[4 * j + 2] = fmaf(v, w.z, a[4 * j + 2]);
        a[4 * j + 3] = fmaf(v, w.w, a[4 * j + 3]);
    }
}
__device__ __forceinline__ void load32(float* a, const float* s) {
    const float4* s4 = reinterpret_cast<const float4*>(s);
#pragma unroll
    for (int j = 0; j < 8; j++) {
        float4 b = s4[j];
        a[4 * j + 0] = b.x; a[4 * j + 1] = b.y;
        a[4 * j + 2] = b.z; a[4 * j + 3] = b.w;
    }
}
__device__ __forceinline__ void relu32(float* a) {
#pragma unroll
    for (int j = 0; j < 32; j++) a[j] = fmaxf(a[j], 0.f);
}

__global__ void __launch_bounds__(64) k_mlp(
    const float* __restrict__ pts, const float* __restrict__ vdirs,
    const float* __restrict__ w0, const float* __restrict__ b0,
    const float* __restrict__ w1, const float* __restrict__ b1,
    const float* __restrict__ fw, const float* __restrict__ fb,
    const float* __restrict__ sw, const float* __restrict__ sb,
    const float* __restrict__ vw, const float* __restrict__ vb,
    const float* __restrict__ rw, const float* __restrict__ rb,
    float* __restrict__ out)
{
    const int vox = blockIdx.x;
    const int tid = threadIdx.x;

    __shared__ float s_tmp[2016];
    __shared__ float s_w0T[2016];   // [d=63][o=32]
    __shared__ float s_w1T[1024];   // [d=32][o=32]
    __shared__ float s_fT[1024];    // [d=32][o=32]
    __shared__ float s_vT[1888];    // [d=59][o=32]
    __shared__ float s_rT[96];      // [d=32][c=3]
    __shared__ float s_sw[32], s_b0[32], s_b1[32], s_fb[32], s_vb[32], s_rb[3], s_sb[1];

    // ---- stage weights (coalesced global -> tmp, conflict-free transpose -> T) ----
    {   // w0: (32,63)
        const float4* g = reinterpret_cast<const float4*>(w0 + (size_t)vox * 2016);
        float4* t = reinterpret_cast<float4*>(s_tmp);
        for (int i = tid; i < 504; i += 64) t[i] = g[i];
        __syncthreads();
        for (int i = tid; i < 2016; i += 64) { int o = i & 31, d = i >> 5; s_w0T[i] = s_tmp[o * 63 + d]; }
        __syncthreads();
    }
    {   // w1: (32,32), padded tmp rows (33) to kill bank conflicts
        const float* g = w1 + (size_t)vox * 1024;
        for (int i = tid; i < 1024; i += 64) s_tmp[(i >> 5) * 33 + (i & 31)] = g[i];
        __syncthreads();
        for (int i = tid; i < 1024; i += 64) { int o = i & 31, d = i >> 5; s_w1T[i] = s_tmp[o * 33 + d]; }
        __syncthreads();
    }
    {   // feat_w: (32,32)
        const float* g = fw + (size_t)vox * 1024;
        for (int i = tid; i < 1024; i += 64) s_tmp[(i >> 5) * 33 + (i & 31)] = g[i];
        __syncthreads();
        for (int i = tid; i < 1024; i += 64) { int o = i & 31, d = i >> 5; s_fT[i] = s_tmp[o * 33 + d]; }
        __syncthreads();
    }
    {   // view_w: (32,59)
        const float4* g = reinterpret_cast<const float4*>(vw + (size_t)vox * 1888);
        float4* t = reinterpret_cast<float4*>(s_tmp);
        for (int i = tid; i < 472; i += 64) t[i] = g[i];
        __syncthreads();
        for (int i = tid; i < 1888; i += 64) { int o = i & 31, d = i >> 5; s_vT[i] = s_tmp[o * 59 + d]; }
        __syncthreads();
    }
    // rgb_w: (3,32) -> rT[d*3+c]; small vectors
    for (int i = tid; i < 96; i += 64) { int c = i >> 5, d = i & 31; s_rT[d * 3 + c] = rw[(size_t)vox * 96 + i]; }
    if (tid < 32) {
        s_sw[tid] = sw[(size_t)vox * 32 + tid];
        s_b0[tid] = b0[(size_t)vox * 32 + tid];
        s_b1[tid] = b1[(size_t)vox * 32 + tid];
        s_fb[tid] = fb[(size_t)vox * 32 + tid];
        s_vb[tid] = vb[(size_t)vox * 32 + tid];
    }
    if (tid < 3) s_rb[tid] = rb[(size_t)vox * 3 + tid];
    if (tid == 0) s_sb[0] = sb[vox];
    __syncthreads();

    const int start = g_start[vox];
    const int count = g_cnt[vox];
    const int warp = tid >> 5, lane = tid & 31;

    for (int base = warp * 32; base < count; base += 64) {
        const int i = base + lane;
        const bool act = (i < count);
        int n = 0;
        float px = 0.f, py = 0.f, pz = 0.f, dvx = 0.f, dvy = 0.f, dvz = 0.f;
        if (act) {
            n = g_sorted[start + i];
            px = pts[3 * n + 0]; py = pts[3 * n + 1]; pz = pts[3 * n + 2];
            int ray = n >> 7;   // N_SAMPLES = 128
            dvx = vdirs[3 * ray + 0]; dvy = vdirs[3 * ray + 1]; dvz = vdirs[3 * ray + 2];
        }

        float A[32], B[32];

        // ---- layer0: 63 -> 32, relu ----
        load32(A, s_b0);
        acc32(A, s_w0T + 0 * 32, px);
        acc32(A, s_w0T + 1 * 32, py);
        acc32(A, s_w0T + 2 * 32, pz);
        {
            float sx = sinf(px), cx = cosf(px);
            float sy = sinf(py), cy = cosf(py);
            float sz = sinf(pz), cz = cosf(pz);
#pragma unroll
            for (int k = 0; k < 10; k++) {
                const float* r = s_w0T + (3 + 6 * k) * 32;
                acc32(A, r + 0 * 32, sx);
                acc32(A, r + 1 * 32, sy);
                acc32(A, r + 2 * 32, sz);
                acc32(A, r + 3 * 32, cx);
                acc32(A, r + 4 * 32, cy);
                acc32(A, r + 5 * 32, cz);
                float nsx = 2.f * sx * cx, ncx = 1.f - 2.f * sx * sx;
                float nsy = 2.f * sy * cy, ncy = 1.f - 2.f * sy * sy;
                float nsz = 2.f * sz * cz, ncz = 1.f - 2.f * sz * sz;
                sx = nsx; cx = ncx; sy = nsy; cy = ncy; sz = nsz; cz = ncz;
            }
        }
        relu32(A);

        // ---- layer1: 32 -> 32, relu ----
        load32(B, s_b1);
#pragma unroll
        for (int d = 0; d < 32; d++) acc32(B, s_w1T + d * 32, A[d]);
        relu32(B);

        // ---- feat: 32 -> 32 (no relu) ----
        load32(A, s_fb);
#pragma unroll
        for (int d = 0; d < 32; d++) acc32(A, s_fT + d * 32, B[d]);

        // ---- sigma: 32 -> 1 ----
        float sg = s_sb[0];
#pragma unroll
        for (int d = 0; d < 32; d++) sg = fmaf(B[d], s_sw[d], sg);

        // ---- view layer: concat(feat[32], ev[27]) -> 32, relu ----
        load32(B, s_vb);
#pragma unroll
        for (int d = 0; d < 32; d++) acc32(B, s_vT + d * 32, A[d]);
        acc32(B, s_vT + 32 * 32, dvx);
        acc32(B, s_vT + 33 * 32, dvy);
        acc32(B, s_vT + 34 * 32, dvz);
        {
            float sx = sinf(dvx), cx = cosf(dvx);
            float sy = sinf(dvy), cy = cosf(dvy);
            float sz = sinf(dvz), cz = cosf(dvz);
#pragma unroll
            for (int k = 0; k < 4; k++) {
                const float* r = s_vT + (35 + 6 * k) * 32;
                acc32(B, r + 0 * 32, sx);
                acc32(B, r + 1 * 32, sy);
                acc32(B, r + 2 * 32, sz);
                acc32(B, r + 3 * 32, cx);
                acc32(B, r + 4 * 32, cy);
                acc32(B, r + 5 * 32, cz);
                float nsx = 2.f * sx * cx, ncx = 1.f - 2.f * sx * sx;
                float nsy = 2.f * sy * cy, ncy = 1.f - 2.f * sy * sy;
                float nsz = 2.f * sz * cz, ncz = 1.f - 2.f * sz * sz;
                sx = nsx; cx = ncx; sy = nsy; cy = ncy; sz = nsz; cz = ncz;
            }
        }
        relu32(B);

        // ---- rgb: 32 -> 3 ----
        float r0 = s_rb[0], r1 = s_rb[1], r2 = s_rb[2];
#pragma unroll
        for (int d = 0; d < 32; d++) {
            r0 = fmaf(B[d], s_rT[d * 3 + 0], r0);
            r1 = fmaf(B[d], s_rT[d * 3 + 1], r1);
            r2 = fmaf(B[d], s_rT[d * 3 + 2], r2);
        }

        if (act) {
            out[3 * n + 0] = r0;
            out[3 * n + 1] = r1;
            out[3 * n + 2] = r2;
            out[(size_t)NPTS * 3 + n] = sg;
        }
    }
}

extern "C" void kernel_launch(void* const* d_in, const int* in_sizes, int n_in,
                              void* d_out, int out_size) {
    (void)in_sizes; (void)n_in; (void)out_size;
    const float* pts = (const float*)d_in[0];
    const float* vd  = (const float*)d_in[1];
    const float* w0  = (const float*)d_in[2];
    const float* b0  = (const float*)d_in[3];
    const float* w1  = (const float*)d_in[4];
    const float* b1  = (const float*)d_in[5];
    const float* fw  = (const float*)d_in[6];
    const float* fb  = (const float*)d_in[7];
    const float* sw  = (const float*)d_in[8];
    const float* sb  = (const float*)d_in[9];
    const float* vw  = (const float*)d_in[10];
    const float* vb  = (const float*)d_in[11];
    const float* rw  = (const float*)d_in[12];
    const float* rb  = (const float*)d_in[13];

    k_zero<<<16, 256>>>();
    k_index<<<512, 256>>>(pts);
    k_scan<<<1, 1024>>>();
    k_scatter<<<512, 256>>>();
    k_mlp<<<NM, 64>>>(pts, vd, w0, b0, w1, b1, fw, fb, sw, sb, vw, vb, rw, rb,
                      (float*)d_out);
}

// round 2
// speedup vs baseline: 1.8784x; 1.8784x over previous
#include <cuda_runtime.h>
#include <math.h>

#define NM      4096
#define NPTS    131072
#define GRES    16

typedef unsigned long long u64;

// ---- scratch (no allocations allowed) ----
__device__ int g_cnt[NM];
__device__ int g_off[NM];
__device__ int g_start[NM];
__device__ int g_vox[NPTS];
__device__ int g_sorted[NPTS];

__global__ void k_zero() {
    int i = blockIdx.x * blockDim.x + threadIdx.x;
    if (i < NM) g_cnt[i] = 0;
}

__global__ void k_index(const float* __restrict__ pts) {
    int n = blockIdx.x * blockDim.x + threadIdx.x;
    if (n >= NPTS) return;
    float x = pts[3 * n + 0], y = pts[3 * n + 1], z = pts[3 * n + 2];
    int ix = (int)fminf(fmaxf(x * (float)GRES, 0.f), (float)(GRES - 1));
    int iy = (int)fminf(fmaxf(y * (float)GRES, 0.f), (float)(GRES - 1));
    int iz = (int)fminf(fmaxf(z * (float)GRES, 0.f), (float)(GRES - 1));
    int v = ix * (GRES * GRES) + iy * GRES + iz;
    g_vox[n] = v;
    atomicAdd(&g_cnt[v], 1);
}

// one block, 1024 threads, 4 bins each
__global__ void k_scan() {
    __shared__ int sh[1024];
    int t = threadIdx.x;
    int c0 = g_cnt[4 * t + 0], c1 = g_cnt[4 * t + 1];
    int c2 = g_cnt[4 * t + 2], c3 = g_cnt[4 * t + 3];
    int s = c0 + c1 + c2 + c3;
    sh[t] = s;
    __syncthreads();
    for (int d = 1; d < 1024; d <<= 1) {
        int v = (t >= d) ? sh[t - d] : 0;
        __syncthreads();
        sh[t] += v;
        __syncthreads();
    }
    int excl = sh[t] - s;
    g_start[4 * t + 0] = excl; g_off[4 * t + 0] = excl; excl += c0;
    g_start[4 * t + 1] = excl; g_off[4 * t + 1] = excl; excl += c1;
    g_start[4 * t + 2] = excl; g_off[4 * t + 2] = excl; excl += c2;
    g_start[4 * t + 3] = excl; g_off[4 * t + 3] = excl;
}

__global__ void k_scatter() {
    int n = blockIdx.x * blockDim.x + threadIdx.x;
    if (n >= NPTS) return;
    int v = g_vox[n];
    int pos = atomicAdd(&g_off[v], 1);
    g_sorted[pos] = n;
}

// ---- packed fp32x2 helpers (FFMA2) ----
__device__ __forceinline__ u64 f2fma(u64 a, u64 b, u64 c) {
    u64 d;
    asm("fma.rn.f32x2 %0, %1, %2, %3;" : "=l"(d) : "l"(a), "l"(b), "l"(c));
    return d;
}
__device__ __forceinline__ u64 pk2(float v) {
    u64 r;
    asm("mov.b64 %0, {%1, %1};" : "=l"(r) : "f"(v));
    return r;
}
__device__ __forceinline__ float2 unpk(u64 p) {
    float2 f;
    asm("mov.b64 {%0, %1}, %2;" : "=f"(f.x), "=f"(f.y) : "l"(p));
    return f;
}
// A[16] packed accumulators += v2 * wrow[0..31]
__device__ __forceinline__ void accP(u64* A, const float* wrow, u64 v2) {
    const ulonglong2* w = reinterpret_cast<const ulonglong2*>(wrow);
#pragma unroll
    for (int j = 0; j < 8; j++) {
        ulonglong2 ww = w[j];
        A[2 * j + 0] = f2fma(v2, ww.x, A[2 * j + 0]);
        A[2 * j + 1] = f2fma(v2, ww.y, A[2 * j + 1]);
    }
}
__device__ __forceinline__ void loadP(u64* A, const float* s) {
    const ulonglong2* b = reinterpret_cast<const ulonglong2*>(s);
#pragma unroll
    for (int j = 0; j < 8; j++) {
        ulonglong2 v = b[j];
        A[2 * j + 0] = v.x;
        A[2 * j + 1] = v.y;
    }
}
__device__ __forceinline__ void unpackRelu(const u64* A, float* H) {
#pragma unroll
    for (int j = 0; j < 16; j++) {
        float2 f = unpk(A[j]);
        H[2 * j + 0] = fmaxf(f.x, 0.f);
        H[2 * j + 1] = fmaxf(f.y, 0.f);
    }
}
__device__ __forceinline__ void unpackPlain(const u64* A, float* H) {
#pragma unroll
    for (int j = 0; j < 16; j++) {
        float2 f = unpk(A[j]);
        H[2 * j + 0] = f.x;
        H[2 * j + 1] = f.y;
    }
}

// ---- staging: (32 x C) row-major -> T[d*32+o], via small tmp, 2 halves ----
__device__ __forceinline__ void stage_odd(const float* g, float* T, float* tmp,
                                          int tid, int C) {
    // C odd (63 or 59): tmp[o*C+d] reads are conflict-free (odd stride)
    for (int h = 0; h < 2; h++) {
        const float4* g4 = reinterpret_cast<const float4*>(g + h * 16 * C);
        float4* t4 = reinterpret_cast<float4*>(tmp);
        int n4 = (16 * C) >> 2;
        for (int i = tid; i < n4; i += 64) t4[i] = g4[i];
        __syncthreads();
        for (int i = tid; i < 16 * C; i += 64) {
            int d = i >> 4, o = i & 15;
            T[d * 32 + h * 16 + o] = tmp[o * C + d];
        }
        __syncthreads();
    }
}
__device__ __forceinline__ void stage32(const float* g, float* T, float* tmp,
                                        int tid) {
    for (int h = 0; h < 2; h++) {
        const float* gh = g + h * 512;
        for (int i = tid; i < 512; i += 64)
            tmp[(i >> 5) * 33 + (i & 31)] = gh[i];
        __syncthreads();
        for (int i = tid; i < 512; i += 64) {
            int d = i >> 4, o = i & 15;
            T[d * 32 + h * 16 + o] = tmp[o * 33 + d];
        }
        __syncthreads();
    }
}

// smem pool layout (floats)
#define OFF_W0T 0
#define OFF_W1T 2016
#define OFF_FT  3040
#define OFF_VT  4064
#define OFF_SM  5952
#define OFF_TMP 6216
#define SP_TOT  7272
// small region inside OFF_SM:
//  sw[32] @0, b0[32] @32, b1[32] @64, fb[32] @96, vb[32] @128,
//  rT[96] @160, rb[3] @256, sb[1] @259

__global__ void __launch_bounds__(64, 7) k_mlp(
    const float* __restrict__ pts, const float* __restrict__ vdirs,
    const float* __restrict__ w0, const float* __restrict__ b0,
    const float* __restrict__ w1, const float* __restrict__ b1,
    const float* __restrict__ fw, const float* __restrict__ fb,
    const float* __restrict__ sw, const float* __restrict__ sb,
    const float* __restrict__ vw, const float* __restrict__ vb,
    const float* __restrict__ rw, const float* __restrict__ rb,
    float* __restrict__ out)
{
    const int vox = blockIdx.x;
    const int tid = threadIdx.x;

    __shared__ __align__(16) float sp[SP_TOT];
    float* s_w0T = sp + OFF_W0T;   // [d=63][o=32]
    float* s_w1T = sp + OFF_W1T;   // [d=32][o=32]
    float* s_fT  = sp + OFF_FT;    // [d=32][o=32]
    float* s_vT  = sp + OFF_VT;    // [d=59][o=32]
    float* s_sm  = sp + OFF_SM;
    float* s_tmp = sp + OFF_TMP;

    stage_odd(w0 + (size_t)vox * 2016, s_w0T, s_tmp, tid, 63);
    stage32(w1 + (size_t)vox * 1024, s_w1T, s_tmp, tid);
    stage32(fw + (size_t)vox * 1024, s_fT, s_tmp, tid);
    stage_odd(vw + (size_t)vox * 1888, s_vT, s_tmp, tid, 59);

    for (int i = tid; i < 96; i += 64) {
        int c = i >> 5, d = i & 31;
        s_sm[160 + d * 3 + c] = rw[(size_t)vox * 96 + i];
    }
    if (tid < 32) {
        s_sm[tid]       = sw[(size_t)vox * 32 + tid];
        s_sm[32 + tid]  = b0[(size_t)vox * 32 + tid];
        s_sm[64 + tid]  = b1[(size_t)vox * 32 + tid];
        s_sm[96 + tid]  = fb[(size_t)vox * 32 + tid];
        s_sm[128 + tid] = vb[(size_t)vox * 32 + tid];
    }
    if (tid < 3) s_sm[256 + tid] = rb[(size_t)vox * 3 + tid];
    if (tid == 0) s_sm[259] = sb[vox];
    __syncthreads();

    const int start = g_start[vox];
    const int count = g_cnt[vox];
    const int warp = tid >> 5, lane = tid & 31;

    for (int base = warp * 32; base < count; base += 64) {
        const int i = base + lane;
        const bool act = (i < count);
        int n = 0;
        float px = 0.f, py = 0.f, pz = 0.f, dvx = 0.f, dvy = 0.f, dvz = 0.f;
        if (act) {
            n = g_sorted[start + i];
            px = pts[3 * n + 0]; py = pts[3 * n + 1]; pz = pts[3 * n + 2];
            int ray = n >> 7;   // N_SAMPLES = 128
            dvx = vdirs[3 * ray + 0]; dvy = vdirs[3 * ray + 1]; dvz = vdirs[3 * ray + 2];
        }

        u64 P[16];
        float A[32], B[32];

        // ---- layer0: 63 -> 32, relu ----
        loadP(P, s_sm + 32);
        accP(P, s_w0T + 0 * 32, pk2(px));
        accP(P, s_w0T + 1 * 32, pk2(py));
        accP(P, s_w0T + 2 * 32, pk2(pz));
        {
            float sx = __sinf(px), cx = __cosf(px);
            float sy = __sinf(py), cy = __cosf(py);
            float sz = __sinf(pz), cz = __cosf(pz);
#pragma unroll
            for (int k = 0; k < 10; k++) {
                const float* r = s_w0T + (3 + 6 * k) * 32;
                accP(P, r + 0 * 32, pk2(sx));
                accP(P, r + 1 * 32, pk2(sy));
                accP(P, r + 2 * 32, pk2(sz));
                accP(P, r + 3 * 32, pk2(cx));
                accP(P, r + 4 * 32, pk2(cy));
                accP(P, r + 5 * 32, pk2(cz));
                float nsx = 2.f * sx * cx, ncx = 1.f - 2.f * sx * sx;
                float nsy = 2.f * sy * cy, ncy = 1.f - 2.f * sy * sy;
                float nsz = 2.f * sz * cz, ncz = 1.f - 2.f * sz * sz;
                sx = nsx; cx = ncx; sy = nsy; cy = ncy; sz = nsz; cz = ncz;
            }
        }
        unpackRelu(P, A);

        // ---- layer1: 32 -> 32, relu ----
        loadP(P, s_sm + 64);
#pragma unroll
        for (int d = 0; d < 32; d++) accP(P, s_w1T + d * 32, pk2(A[d]));
        unpackRelu(P, B);

        // ---- sigma: 32 -> 1 (from B) ----
        float sg = s_sm[259];
#pragma unroll
        for (int d = 0; d < 32; d++) sg = fmaf(B[d], s_sm[d], sg);

        // ---- feat: 32 -> 32 (no relu), consumes B, produces A ----
        loadP(P, s_sm + 96);
#pragma unroll
        for (int d = 0; d < 32; d++) accP(P, s_fT + d * 32, pk2(B[d]));
        unpackPlain(P, A);

        // ---- view layer: concat(feat[32], ev[27]) -> 32, relu ----
        loadP(P, s_sm + 128);
#pragma unroll
        for (int d = 0; d < 32; d++) accP(P, s_vT + d * 32, pk2(A[d]));
        accP(P, s_vT + 32 * 32, pk2(dvx));
        accP(P, s_vT + 33 * 32, pk2(dvy));
        accP(P, s_vT + 34 * 32, pk2(dvz));
        {
            float sx = __sinf(dvx), cx = __cosf(dvx);
            float sy = __sinf(dvy), cy = __cosf(dvy);
            float sz = __sinf(dvz), cz = __cosf(dvz);
#pragma unroll
            for (int k = 0; k < 4; k++) {
                const float* r = s_vT + (35 + 6 * k) * 32;
                accP(P, r + 0 * 32, pk2(sx));
                accP(P, r + 1 * 32, pk2(sy));
                accP(P, r + 2 * 32, pk2(sz));
                accP(P, r + 3 * 32, pk2(cx));
                accP(P, r + 4 * 32, pk2(cy));
                accP(P, r + 5 * 32, pk2(cz));
                float nsx = 2.f * sx * cx, ncx = 1.f - 2.f * sx * sx;
                float nsy = 2.f * sy * cy, ncy = 1.f - 2.f * sy * sy;
                float nsz = 2.f * sz * cz, ncz = 1.f - 2.f * sz * sz;
                sx = nsx; cx = ncx; sy = nsy; cy = ncy; sz = nsz; cz = ncz;
            }
        }
        unpackRelu(P, B);

        // ---- rgb: 32 -> 3 ----
        float r0 = s_sm[256], r1 = s_sm[257], r2 = s_sm[258];
#pragma unroll
        for (int d = 0; d < 32; d++) {
            r0 = fmaf(B[d], s_sm[160 + d * 3 + 0], r0);
            r1 = fmaf(B[d], s_sm[160 + d * 3 + 1], r1);
            r2 = fmaf(B[d], s_sm[160 + d * 3 + 2], r2);
        }

        if (act) {
            out[3 * n + 0] = r0;
            out[3 * n + 1] = r1;
            out[3 * n + 2] = r2;
            out[(size_t)NPTS * 3 + n] = sg;
        }
    }
}

extern "C" void kernel_launch(void* const* d_in, const int* in_sizes, int n_in,
                              void* d_out, int out_size) {
    (void)in_sizes; (void)n_in; (void)out_size;
    const float* pts = (const float*)d_in[0];
    const float* vd  = (const float*)d_in[1];
    const float* w0  = (const float*)d_in[2];
    const float* b0  = (const float*)d_in[3];
    const float* w1  = (const float*)d_in[4];
    const float* b1  = (const float*)d_in[5];
    const float* fw  = (const float*)d_in[6];
    const float* fb  = (const float*)d_in[7];
    const float* sw  = (const float*)d_in[8];
    const float* sb  = (const float*)d_in[9];
    const float* vw  = (const float*)d_in[10];
    const float* vb  = (const float*)d_in[11];
    const float* rw  = (const float*)d_in[12];
    const float* rb  = (const float*)d_in[13];

    k_zero<<<16, 256>>>();
    k_index<<<512, 256>>>(pts);
    k_scan<<<1, 1024>>>();
    k_scatter<<<512, 256>>>();
    k_mlp<<<NM, 64>>>(pts, vd, w0, b0, w1, b1, fw, fb, sw, sb, vw, vb, rw, rb,
                      (float*)d_out);
}